// round 6
// baseline (speedup 1.0000x reference)
#include <cuda_runtime.h>
#include <cuda_bf16.h>

#define BATCH   32768
#define HID     128
#define INF     784
#define NCLS    10
#define TSTEPS  20

#define DECAYF  0.25f
#define THRESHF 1.0f
#define EPSM    2e-4f

#define KCHUNKS (INF / 16)      // 49
#define FIXCAP  (1 << 21)

// Scratch (device globals)
__device__ float    g_c2[(size_t)TSTEPS * BATCH * NCLS];
__device__ unsigned g_fix_list[FIXCAP];
__device__ unsigned g_fix_cnt;
__device__ __align__(16) unsigned short g_w1a[HID * INF];   // bf16 hi plane
__device__ __align__(16) unsigned short g_w1b[HID * INF];   // bf16 lo plane

// ---------------------------------------------------------------------------
__device__ __forceinline__ void split2(float v, unsigned short& h0, unsigned short& h1)
{
    __nv_bfloat16 b0 = __float2bfloat16_rn(v);
    float r = v - __bfloat162float(b0);
    __nv_bfloat16 b1 = __float2bfloat16_rn(r);
    h0 = __bfloat16_as_ushort(b0);
    h1 = __bfloat16_as_ushort(b1);
}

__device__ __forceinline__ void mma_bf16(float* d, const unsigned* a, const unsigned* b)
{
    asm volatile(
        "mma.sync.aligned.m16n8k16.row.col.f32.bf16.bf16.f32 "
        "{%0,%1,%2,%3}, {%4,%5,%6,%7}, {%8,%9}, {%0,%1,%2,%3};"
        : "+f"(d[0]), "+f"(d[1]), "+f"(d[2]), "+f"(d[3])
        : "r"(a[0]), "r"(a[1]), "r"(a[2]), "r"(a[3]), "r"(b[0]), "r"(b[1]));
}

__device__ __forceinline__ void cp_async16(void* smem, const void* gmem)
{
    unsigned saddr = (unsigned)__cvta_generic_to_shared(smem);
    asm volatile("cp.async.cg.shared.global [%0], [%1], 16;"
                 :: "r"(saddr), "l"(gmem));
}
#define CP_COMMIT() asm volatile("cp.async.commit_group;")
#define CP_WAIT2()  asm volatile("cp.async.wait_group 2;" ::: "memory")

__global__ void k0_init(const float* __restrict__ W1)
{
    if (blockIdx.x == 0 && threadIdx.x == 0) g_fix_cnt = 0;
    int i = blockIdx.x * blockDim.x + threadIdx.x;
    if (i < HID * INF) {
        unsigned short h0, h1;
        split2(W1[i], h0, h1);
        g_w1a[i] = h0;
        g_w1b[i] = h1;
    }
}

// ---------------------------------------------------------------------------
// K1: cur1 via bf16x2-split (3 MMA products), pipelined:
//   B (pre-split W1): cp.async 4-stage, distance-3 lookahead.
//   A (x): register prefetch distance-2, split2 one iter after LDG.
// Fused 20-step LIF epilogue with margin tracking (unchanged from R5).
// ---------------------------------------------------------------------------
#define ASTRIDE 24   // A smem row stride (ushorts) - conflict-free frag LDS
#define BSTRIDE 16   // B smem row stride (ushorts) - 2-way conflict, cheap

__global__ __launch_bounds__(256) void k1_mma(
    const float* __restrict__ x, const float* __restrict__ b1,
    float* __restrict__ out_spk)
{
    __shared__ unsigned short Bst[4][2][128 * BSTRIDE];   // 32 KB
    __shared__ unsigned short Asb[2][2][64 * ASTRIDE];    // 12 KB

    const int tid  = threadIdx.x;
    const int lane = tid & 31;
    const int wid  = tid >> 5;
    const int g    = lane >> 2;
    const int tg   = lane & 3;
    const int wm   = wid >> 2;
    const int wn   = wid & 3;
    const int m0   = blockIdx.x * 64;

    const int sm  = tid >> 2;           // A stage row 0..63
    const int skq = (tid & 3) * 4;      // A stage k 0,4,8,12
    const int bn  = tid >> 1;           // B stage n 0..127
    const int bkh = (tid & 1) * 8;      // B stage k half (0 or 8)

    float acc[2][4][4];
    #pragma unroll
    for (int mt = 0; mt < 2; mt++)
        #pragma unroll
        for (int nt = 0; nt < 4; nt++)
            #pragma unroll
            for (int r = 0; r < 4; r++) acc[mt][nt][r] = 0.0f;

    // ---- pipeline prologue ----
    // B chunks 0,1,2 via cp.async (groups 0,1,2)
    #pragma unroll
    for (int c = 0; c < 3; c++) {
        int k0 = c * 16;
        cp_async16(&Bst[c][0][bn * BSTRIDE + bkh], &g_w1a[bn * INF + k0 + bkh]);
        cp_async16(&Bst[c][1][bn * BSTRIDE + bkh], &g_w1b[bn * INF + k0 + bkh]);
        CP_COMMIT();
    }
    // A chunk 0: load + split + store; A chunk 1: load, hold in regs
    float4 rA;
    {
        float4 a0 = *reinterpret_cast<const float4*>(&x[(size_t)(m0 + sm) * INF + skq]);
        float av[4] = {a0.x, a0.y, a0.z, a0.w};
        unsigned short p0[4], p1[4];
        #pragma unroll
        for (int i = 0; i < 4; i++) split2(av[i], p0[i], p1[i]);
        *reinterpret_cast<uint2*>(&Asb[0][0][sm * ASTRIDE + skq]) = *reinterpret_cast<uint2*>(p0);
        *reinterpret_cast<uint2*>(&Asb[0][1][sm * ASTRIDE + skq]) = *reinterpret_cast<uint2*>(p1);
        rA = *reinterpret_cast<const float4*>(&x[(size_t)(m0 + sm) * INF + 16 + skq]);
    }
    CP_WAIT2();               // group 0 (B chunk 0) complete
    __syncthreads();

    // ---- mainloop: invariant entering iter kc: rA holds A chunk kc+1,
    //      Asb[kc%2] holds A chunk kc, Bst[kc%4] holds B chunk kc. ----
    for (int kc = 0; kc < KCHUNKS; kc++) {
        // issue A LDG for chunk kc+2
        float4 rA2;
        if (kc + 2 < KCHUNKS)
            rA2 = *reinterpret_cast<const float4*>(
                &x[(size_t)(m0 + sm) * INF + (kc + 2) * 16 + skq]);

        // fragments
        const int ab = kc & 1;
        const int bs = kc & 3;
        unsigned aF[2][2][4];
        #pragma unroll
        for (int s = 0; s < 2; s++)
            #pragma unroll
            for (int mt = 0; mt < 2; mt++) {
                const unsigned short* ap = &Asb[ab][s][(wm * 32 + mt * 16) * ASTRIDE];
                aF[s][mt][0] = *reinterpret_cast<const unsigned*>(&ap[(g)     * ASTRIDE + tg * 2]);
                aF[s][mt][1] = *reinterpret_cast<const unsigned*>(&ap[(g + 8) * ASTRIDE + tg * 2]);
                aF[s][mt][2] = *reinterpret_cast<const unsigned*>(&ap[(g)     * ASTRIDE + tg * 2 + 8]);
                aF[s][mt][3] = *reinterpret_cast<const unsigned*>(&ap[(g + 8) * ASTRIDE + tg * 2 + 8]);
            }
        unsigned bF[2][4][2];
        #pragma unroll
        for (int s = 0; s < 2; s++)
            #pragma unroll
            for (int nt = 0; nt < 4; nt++) {
                const unsigned short* bp = &Bst[bs][s][(wn * 32 + nt * 8 + g) * BSTRIDE];
                bF[s][nt][0] = *reinterpret_cast<const unsigned*>(&bp[tg * 2]);
                bF[s][nt][1] = *reinterpret_cast<const unsigned*>(&bp[tg * 2 + 8]);
            }

        // 3 split-products: a0b0, a0b1, a1b0
        #pragma unroll
        for (int p = 0; p < 3; p++) {
            const int PI[3] = {0, 0, 1};
            const int PJ[3] = {0, 1, 0};
            int i = PI[p], j = PJ[p];
            #pragma unroll
            for (int mt = 0; mt < 2; mt++)
                #pragma unroll
                for (int nt = 0; nt < 4; nt++)
                    mma_bf16(acc[mt][nt], aF[i][mt], bF[j][nt]);
        }

        // split + store A chunk kc+1 into Asb[(kc+1)%2]
        if (kc + 1 < KCHUNKS) {
            int ob = (kc + 1) & 1;
            float av[4] = {rA.x, rA.y, rA.z, rA.w};
            unsigned short p0[4], p1[4];
            #pragma unroll
            for (int i = 0; i < 4; i++) split2(av[i], p0[i], p1[i]);
            *reinterpret_cast<uint2*>(&Asb[ob][0][sm * ASTRIDE + skq]) = *reinterpret_cast<uint2*>(p0);
            *reinterpret_cast<uint2*>(&Asb[ob][1][sm * ASTRIDE + skq]) = *reinterpret_cast<uint2*>(p1);
        }

        // issue B chunk kc+3 into stage (kc+3)%4 (stage last read at iter kc-1)
        if (kc + 3 < KCHUNKS) {
            int st = (kc + 3) & 3;
            int k0 = (kc + 3) * 16;
            cp_async16(&Bst[st][0][bn * BSTRIDE + bkh], &g_w1a[bn * INF + k0 + bkh]);
            cp_async16(&Bst[st][1][bn * BSTRIDE + bkh], &g_w1b[bn * INF + k0 + bkh]);
        }
        CP_COMMIT();          // one group per iter (possibly empty at tail)

        rA = rA2;
        CP_WAIT2();           // B chunk kc+1 complete
        __syncthreads();
    }

    // ---- epilogue: + b1, LIF with margin tracking, write spikes ----
    float cur[2][4][4];
    #pragma unroll
    for (int nt = 0; nt < 4; nt++) {
        float2 bv = *reinterpret_cast<const float2*>(&b1[wn * 32 + nt * 8 + tg * 2]);
        #pragma unroll
        for (int mt = 0; mt < 2; mt++) {
            cur[mt][nt][0] = acc[mt][nt][0] + bv.x;
            cur[mt][nt][1] = acc[mt][nt][1] + bv.y;
            cur[mt][nt][2] = acc[mt][nt][2] + bv.x;
            cur[mt][nt][3] = acc[mt][nt][3] + bv.y;
        }
    }

    float mem[2][4][4];
    unsigned badm[2][4];
    #pragma unroll
    for (int mt = 0; mt < 2; mt++)
        #pragma unroll
        for (int nt = 0; nt < 4; nt++) {
            badm[mt][nt] = 0u;
            #pragma unroll
            for (int r = 0; r < 4; r++) mem[mt][nt][r] = 0.0f;
        }

    for (int t = 0; t < TSTEPS; t++) {
        float* pt = out_spk + (size_t)t * ((size_t)BATCH * HID);
        #pragma unroll
        for (int mt = 0; mt < 2; mt++) {
            int r0 = m0 + wm * 32 + mt * 16 + g;
            #pragma unroll
            for (int nt = 0; nt < 4; nt++) {
                int n = wn * 32 + nt * 8 + tg * 2;
                float s[4];
                #pragma unroll
                for (int r = 0; r < 4; r++) {
                    float m = fmaf(mem[mt][nt][r], DECAYF, cur[mt][nt][r]);
                    if (fabsf(m - THRESHF) < EPSM) badm[mt][nt] |= (1u << r);
                    s[r] = (m > THRESHF) ? 1.0f : 0.0f;
                    mem[mt][nt][r] = (s[r] != 0.0f) ? 0.0f : m;
                }
                float2 v0 = {s[0], s[1]};
                float2 v1 = {s[2], s[3]};
                *reinterpret_cast<float2*>(&pt[(size_t)r0 * HID + n])       = v0;
                *reinterpret_cast<float2*>(&pt[(size_t)(r0 + 8) * HID + n]) = v1;
            }
        }
    }

    #pragma unroll
    for (int mt = 0; mt < 2; mt++)
        #pragma unroll
        for (int nt = 0; nt < 4; nt++)
            if (badm[mt][nt]) {
                #pragma unroll
                for (int r = 0; r < 4; r++)
                    if (badm[mt][nt] & (1u << r)) {
                        int row = m0 + wm * 32 + mt * 16 + g + ((r >> 1) ? 8 : 0);
                        int col = wn * 32 + nt * 8 + tg * 2 + (r & 1);
                        unsigned pos = atomicAdd(&g_fix_cnt, 1u);
                        if (pos < FIXCAP)
                            g_fix_list[pos] = (unsigned)(row * HID + col);
                    }
            }
}

// ---------------------------------------------------------------------------
// K1b fixup: exact sequential-k fp32 recompute (bitwise R1 recipe).
// ---------------------------------------------------------------------------
__global__ __launch_bounds__(128) void k1_fixup(
    const float* __restrict__ x, const float* __restrict__ W1,
    const float* __restrict__ b1, float* __restrict__ out_spk)
{
    const unsigned cnt = min(*(volatile unsigned*)&g_fix_cnt, (unsigned)FIXCAP);
    const int stride = gridDim.x * blockDim.x;

    for (unsigned i = blockIdx.x * blockDim.x + threadIdx.x; i < cnt; i += stride) {
        unsigned idx = g_fix_list[i];
        int b = idx >> 7;
        int j = idx & (HID - 1);

        const float* xr = x  + (size_t)b * INF;
        const float* wr = W1 + (size_t)j * INF;
        float a = 0.0f;
        for (int k = 0; k < INF; k++)
            a = fmaf(__ldg(&xr[k]), __ldg(&wr[k]), a);
        float curv = a + __ldg(&b1[j]);

        float m = 0.0f;
        for (int t = 0; t < TSTEPS; t++) {
            m = fmaf(m, DECAYF, curv);
            float s = (m > THRESHF) ? 1.0f : 0.0f;
            out_spk[(size_t)t * ((size_t)BATCH * HID) + idx] = s;
            m = (s != 0.0f) ? 0.0f : m;
        }
    }
}

// ---------------------------------------------------------------------------
// K3: c2 = spk @ W2^T, double-buffered 16-col chunks with register prefetch.
// FMA chain: ascending j, same order as R1 -> bitwise identical results.
// ---------------------------------------------------------------------------
__global__ __launch_bounds__(256) void k3_gemm2(
    const float* __restrict__ spk, const float* __restrict__ W2)
{
    __shared__ float sh[2][256][17];     // 2 x 256 rows x 16 cols (pad 17)
    __shared__ float W2t[HID][12];

    const int tid = threadIdx.x;
    for (int i = tid; i < HID * NCLS; i += 256) {
        int j = i / NCLS;
        int o = i - j * NCLS;
        W2t[j][o] = W2[o * HID + j];
    }

    const size_t row0 = (size_t)blockIdx.x * 256;
    float acc[NCLS];
    #pragma unroll
    for (int o = 0; o < NCLS; o++) acc[o] = 0.0f;

    // prefetch chunk 0 (4 float4 per thread)
    float4 v[4];
    #pragma unroll
    for (int s4 = 0; s4 < 4; s4++) {
        int f = tid + s4 * 256;          // 0..1023 float4 slots
        int r = f >> 2;
        int q = f & 3;
        v[s4] = *reinterpret_cast<const float4*>(&spk[(row0 + r) * HID + q * 4]);
    }

    for (int jc = 0; jc < 8; jc++) {
        int buf = jc & 1;
        // store current chunk to smem
        #pragma unroll
        for (int s4 = 0; s4 < 4; s4++) {
            int f = tid + s4 * 256;
            int r = f >> 2;
            int q = f & 3;
            sh[buf][r][q * 4 + 0] = v[s4].x;
            sh[buf][r][q * 4 + 1] = v[s4].y;
            sh[buf][r][q * 4 + 2] = v[s4].z;
            sh[buf][r][q * 4 + 3] = v[s4].w;
        }
        // prefetch next chunk
        if (jc < 7) {
            #pragma unroll
            for (int s4 = 0; s4 < 4; s4++) {
                int f = tid + s4 * 256;
                int r = f >> 2;
                int q = f & 3;
                v[s4] = *reinterpret_cast<const float4*>(
                    &spk[(row0 + r) * HID + (jc + 1) * 16 + q * 4]);
            }
        }
        __syncthreads();
        // compute this chunk (ascending j)
        #pragma unroll
        for (int j = 0; j < 16; j++) {
            float s = sh[buf][tid][j];
            const float* wr = W2t[jc * 16 + j];
            float4 w0 = *reinterpret_cast<const float4*>(wr);
            float4 w1 = *reinterpret_cast<const float4*>(wr + 4);
            float2 w2 = *reinterpret_cast<const float2*>(wr + 8);
            acc[0] = fmaf(s, w0.x, acc[0]);
            acc[1] = fmaf(s, w0.y, acc[1]);
            acc[2] = fmaf(s, w0.z, acc[2]);
            acc[3] = fmaf(s, w0.w, acc[3]);
            acc[4] = fmaf(s, w1.x, acc[4]);
            acc[5] = fmaf(s, w1.y, acc[5]);
            acc[6] = fmaf(s, w1.z, acc[6]);
            acc[7] = fmaf(s, w1.w, acc[7]);
            acc[8] = fmaf(s, w2.x, acc[8]);
            acc[9] = fmaf(s, w2.y, acc[9]);
        }
    }

    const size_t r = row0 + tid;
    #pragma unroll
    for (int o = 0; o < NCLS; o++)
        g_c2[r * NCLS + o] = acc[o];
}

// ---------------------------------------------------------------------------
__global__ __launch_bounds__(256) void k4_lif2(
    const float* __restrict__ b2, float* __restrict__ outp)
{
    const int id = blockIdx.x * blockDim.x + threadIdx.x;
    const int o = id % NCLS;
    const float bias = __ldg(&b2[o]);

    float mem = 0.0f, acc = 0.0f;
    #pragma unroll
    for (int t = 0; t < TSTEPS; t++) {
        float v = fmaf(mem, DECAYF, g_c2[(size_t)t * (BATCH * NCLS) + id]);
        v = v + bias;
        float s = (v > THRESHF) ? 1.0f : 0.0f;
        acc += s;
        mem = (s != 0.0f) ? 0.0f : v;
    }
    outp[id] = acc;
}

// ---------------------------------------------------------------------------
extern "C" void kernel_launch(void* const* d_in, const int* in_sizes, int n_in,
                              void* d_out, int out_size)
{
    const float* x  = (const float*)d_in[0];
    const float* W1 = (const float*)d_in[1];
    const float* b1 = (const float*)d_in[2];
    const float* W2 = (const float*)d_in[3];
    const float* b2 = (const float*)d_in[4];
    float* out = (float*)d_out;

    float* out_output = out;
    float* out_spk    = out + (size_t)BATCH * NCLS;

    k0_init<<<(HID * INF + 255) / 256, 256>>>(W1);
    k1_mma<<<BATCH / 64, 256>>>(x, b1, out_spk);
    k1_fixup<<<256, 128>>>(x, W1, b1, out_spk);
    k3_gemm2<<<(TSTEPS * BATCH) / 256, 256>>>(out_spk, W2);
    k4_lif2<<<(BATCH * NCLS) / 256, 256>>>(b2, out_output);
}